// round 9
// baseline (speedup 1.0000x reference)
#include <cuda_runtime.h>
#include <cstdint>

// Problem constants (fixed by setup_inputs: B=32, NT=32, NP=8192)
// Total f4 = 32*32*8192*3/4 = 6,291,456 ; slab (b,t) = 6144 f4 = 8 tiles of 768.
#define THREADS 256
#define TILE_F4 768            // 12288 B = 256 threads * 3 f4 (4 whole points/thread)
#define TILE_BYTES 12288
#define TPB 4                  // tiles per block, all loads issued up-front
#define GRID 2048              // 2048 * 4 * 768 = 6,291,456 f4 (exact)
#define SMEM_DYN (TPB * TILE_BYTES)   // 49152 B

__device__ __forceinline__ uint32_t smem_u32(const void* p) {
    return (uint32_t)__cvta_generic_to_shared(p);
}
__device__ __forceinline__ void mbar_init(uint32_t a, uint32_t cnt) {
    asm volatile("mbarrier.init.shared.b64 [%0], %1;" :: "r"(a), "r"(cnt) : "memory");
}
__device__ __forceinline__ void mbar_expect_tx(uint32_t a, uint32_t bytes) {
    asm volatile("mbarrier.arrive.expect_tx.shared.b64 _, [%0], %1;"
                 :: "r"(a), "r"(bytes) : "memory");
}
__device__ __forceinline__ void bulk_g2s(uint32_t dst, const void* src,
                                         uint32_t bytes, uint32_t mbar) {
    asm volatile("cp.async.bulk.shared::cta.global.mbarrier::complete_tx::bytes "
                 "[%0], [%1], %2, [%3];"
                 :: "r"(dst), "l"(src), "r"(bytes), "r"(mbar) : "memory");
}
__device__ __forceinline__ void bulk_s2g(void* dst, uint32_t src, uint32_t bytes) {
    asm volatile("cp.async.bulk.global.shared::cta.bulk_group [%0], [%1], %2;"
                 :: "l"(dst), "r"(src), "r"(bytes) : "memory");
}
__device__ __forceinline__ void bulk_commit() {
    asm volatile("cp.async.bulk.commit_group;" ::: "memory");
}
__device__ __forceinline__ void bulk_wait_all() {
    asm volatile("cp.async.bulk.wait_group 0;" ::: "memory");
}
__device__ __forceinline__ void fence_async_shared() {
    asm volatile("fence.proxy.async.shared::cta;" ::: "memory");
}
__device__ __forceinline__ void mbar_wait_parity(uint32_t a, uint32_t parity) {
    asm volatile(
        "{\n\t"
        ".reg .pred P;\n\t"
        "WL_%=:\n\t"
        "mbarrier.try_wait.parity.acquire.cta.shared::cta.b64 P, [%0], %1, 0x989680;\n\t"
        "@P bra WD_%=;\n\t"
        "bra.uni WL_%=;\n\t"
        "WD_%=:\n\t"
        "}"
        :: "r"(a), "r"(parity) : "memory");
}

__global__ __launch_bounds__(THREADS) void fused_xform_kernel(
    const float4* __restrict__ X, const float* __restrict__ dof,
    float4* __restrict__ out)
{
    extern __shared__ __align__(16) float4 buf[];      // [TPB][TILE_F4]
    __shared__ unsigned long long mbar[TPB];

    const int tid  = threadIdx.x;
    const int blk  = blockIdx.x;
    const int slab = blk >> 1;                 // 2 blocks per slab

    // ---- init barriers, then kick off ALL tile loads (engine-held MLP) ----
    if (tid == 0) {
        #pragma unroll
        for (int s = 0; s < TPB; s++) mbar_init(smem_u32(&mbar[s]), 1);
        fence_async_shared();
    }
    __syncthreads();
    if (tid == 0) {
        const long gbase = (long)blk * (TPB * TILE_F4);
        #pragma unroll
        for (int s = 0; s < TPB; s++) {
            mbar_expect_tx(smem_u32(&mbar[s]), TILE_BYTES);
            bulk_g2s(smem_u32(&buf[s * TILE_F4]), &X[gbase + s * TILE_F4],
                     TILE_BYTES, smem_u32(&mbar[s]));
        }
    }

    // ---- per-slab SE(3) exp (all threads, overlaps the bulk-load latency) ----
    const float* dd = dof + slab * 6;
    float vx = dd[0], vy = dd[1], vz = dd[2];
    float wx = dd[3], wy = dd[4], wz = dd[5];
    float t2 = wx*wx + wy*wy + wz*wz;
    float th = sqrtf(t2);
    float A, B, C;
    if (th < 1e-4f) {
        A = 1.0f - t2 * (1.0f/6.0f);
        B = 0.5f - t2 * (1.0f/24.0f);
        C = (1.0f/6.0f) - t2 * (1.0f/120.0f);
    } else {
        float s, c;
        sincosf(th, &s, &c);
        A = s / th;
        B = (1.0f - c) / t2;
        C = (th - s) / (t2 * th);
    }
    // K^2 = w w^T - t2*I
    const float r00 = 1.0f + B*(wx*wx - t2);
    const float r01 = -A*wz + B*wx*wy;
    const float r02 =  A*wy + B*wx*wz;
    const float r10 =  A*wz + B*wx*wy;
    const float r11 = 1.0f + B*(wy*wy - t2);
    const float r12 = -A*wx + B*wy*wz;
    const float r20 = -A*wy + B*wx*wz;
    const float r21 =  A*wx + B*wy*wz;
    const float r22 = 1.0f + B*(wz*wz - t2);

    const float v00 = 1.0f + C*(wx*wx - t2);
    const float v01 = -B*wz + C*wx*wy;
    const float v02 =  B*wy + C*wx*wz;
    const float v10 =  B*wz + C*wx*wy;
    const float v11 = 1.0f + C*(wy*wy - t2);
    const float v12 = -B*wx + C*wy*wz;
    const float v20 = -B*wy + C*wx*wz;
    const float v21 =  B*wx + C*wy*wz;
    const float v22 = 1.0f + C*(wz*wz - t2);

    const float tx = v00*vx + v01*vy + v02*vz;
    const float ty = v10*vx + v11*vy + v12*vz;
    const float tz = v20*vx + v21*vy + v22*vz;

    // ---- tiles: wait -> transform in place -> async bulk store ----
    #pragma unroll
    for (int it = 0; it < TPB; it++) {
        mbar_wait_parity(smem_u32(&mbar[it]), 0);

        float4* tb = &buf[it * TILE_F4];

        // lane owns f4 slots 3*tid..3*tid+2 = 4 whole points (self-contained)
        float4 a = tb[3 * tid + 0];
        float4 b = tb[3 * tid + 1];
        float4 c = tb[3 * tid + 2];

        // p0=(a.x,a.y,a.z) p1=(a.w,b.x,b.y) p2=(b.z,b.w,c.x) p3=(c.y,c.z,c.w)
        float ox0 = fmaf(r00, a.x, fmaf(r01, a.y, fmaf(r02, a.z, tx)));
        float oy0 = fmaf(r10, a.x, fmaf(r11, a.y, fmaf(r12, a.z, ty)));
        float oz0 = fmaf(r20, a.x, fmaf(r21, a.y, fmaf(r22, a.z, tz)));

        float ox1 = fmaf(r00, a.w, fmaf(r01, b.x, fmaf(r02, b.y, tx)));
        float oy1 = fmaf(r10, a.w, fmaf(r11, b.x, fmaf(r12, b.y, ty)));
        float oz1 = fmaf(r20, a.w, fmaf(r21, b.x, fmaf(r22, b.y, tz)));

        float ox2 = fmaf(r00, b.z, fmaf(r01, b.w, fmaf(r02, c.x, tx)));
        float oy2 = fmaf(r10, b.z, fmaf(r11, b.w, fmaf(r12, c.x, ty)));
        float oz2 = fmaf(r20, b.z, fmaf(r21, b.w, fmaf(r22, c.x, tz)));

        float ox3 = fmaf(r00, c.y, fmaf(r01, c.z, fmaf(r02, c.w, tx)));
        float oy3 = fmaf(r10, c.y, fmaf(r11, c.z, fmaf(r12, c.w, ty)));
        float oz3 = fmaf(r20, c.y, fmaf(r21, c.z, fmaf(r22, c.w, tz)));

        // overwrite own slots (no cross-thread hazard)
        tb[3 * tid + 0] = make_float4(ox0, oy0, oz0, ox1);
        tb[3 * tid + 1] = make_float4(oy1, oz1, ox2, oy2);
        tb[3 * tid + 2] = make_float4(oz2, ox3, oy3, oz3);

        __syncthreads();          // all lanes' results in smem
        if (tid == 0) {
            fence_async_shared(); // order generic STS before async-proxy read
            bulk_s2g(&out[(long)blk * (TPB * TILE_F4) + (long)it * TILE_F4],
                     smem_u32(tb), TILE_BYTES);
            bulk_commit();
        }
    }

    // keep CTA alive until bulk stores have read smem
    if (tid == 0) bulk_wait_all();
}

extern "C" void kernel_launch(void* const* d_in, const int* in_sizes, int n_in,
                              void* d_out, int out_size) {
    const float4* X   = (const float4*)d_in[0];   // X_v: 32*32*8192*3 f32
    const float*  dof = (const float*)d_in[1];    // dof: 32*32*6 f32
    float4* out = (float4*)d_out;

    cudaFuncSetAttribute(fused_xform_kernel,
                         cudaFuncAttributeMaxDynamicSharedMemorySize, SMEM_DYN);
    fused_xform_kernel<<<GRID, THREADS, SMEM_DYN>>>(X, dof, out);
}